// round 3
// baseline (speedup 1.0000x reference)
#include <cuda_runtime.h>
#include <cuda_bf16.h>

// Problem constants (static per reference)
#define N_MOL    2000
#define ASZ      64
#define PPM      (ASZ * (ASZ - 1))          // 4032 pairs per molecule
#define NPAIR    ((long long)N_MOL * PPM)   // 8,064,000
#define NTHREADS 224                        // 7 full warps
#define NITER    18                         // 224 * 18 = 4032

// Output layout (flattened tuple concat, fp32):
//   [0   ,  P) : i indices (as float)
//   [P   , 2P) : j indices (as float)
//   [2P  , 3P) : d_ij
//   [3P  , 6P) : r_ij row-major [P,3]

__global__ __launch_bounds__(NTHREADS, 9)
void pairlist_kernel(const float* __restrict__ pos, float* __restrict__ out)
{
    __shared__ float s[ASZ * 3];          // xyz interleaved positions
    __shared__ float rbuf[7][2][96];      // per-warp double-buffered r transpose

    const int m = blockIdx.x;
    const int t = threadIdx.x;
    const int w = t >> 5;
    const int l = t & 31;

    // Stage this molecule's 64 positions (192 floats) into shared
    const float* pm = pos + (size_t)m * (ASZ * 3);
    if (t < ASZ * 3) s[t] = pm[t];
    __syncthreads();

    float* __restrict__ out_i = out;
    float* __restrict__ out_j = out + NPAIR;
    float* __restrict__ out_d = out + 2 * NPAIR;
    float* __restrict__ out_r = out + 3 * NPAIR;

    const size_t base  = (size_t)m * PPM;
    const int    ibase = m * ASZ;

    #pragma unroll
    for (int it = 0; it < NITER; it++) {
        const unsigned q     = (unsigned)t + (unsigned)NTHREADS * it; // pair-in-molecule
        const unsigned i_loc = q / 63u;                               // magic-mul div
        const unsigned k     = q - 63u * i_loc;
        const unsigned j_loc = k + (k >= i_loc ? 1u : 0u);

        const float xi = s[3 * i_loc + 0];    // near-broadcast reads
        const float yi = s[3 * i_loc + 1];
        const float zi = s[3 * i_loc + 2];
        const float rx = s[3 * j_loc + 0] - xi;
        const float ry = s[3 * j_loc + 1] - yi;
        const float rz = s[3 * j_loc + 2] - zi;
        const float d  = sqrtf(fmaf(rx, rx, fmaf(ry, ry, rz * rz)));

        const size_t p = base + q;
        out_i[p] = (float)(ibase + (int)i_loc);
        out_j[p] = (float)(ibase + (int)j_loc);
        out_d[p] = d;

        // --- r_ij: per-warp transpose through smem -> 3 contiguous 128B stores ---
        float* rb = rbuf[w][it & 1];
        rb[3 * l + 0] = rx;   // banks 3l+c mod 32: conflict-free (gcd(3,32)=1)
        rb[3 * l + 1] = ry;
        rb[3 * l + 2] = rz;
        __syncwarp();
        const size_t rb0 = 3 * (base + (size_t)(q - (unsigned)l)); // warp-chunk base
        out_r[rb0 + l +  0] = rb[l +  0];   // stride-1 reads, contiguous stores
        out_r[rb0 + l + 32] = rb[l + 32];
        out_r[rb0 + l + 64] = rb[l + 64];
        // double buffer: iteration it+2 writes this buffer only after the
        // __syncwarp() of iteration it+1, which orders these reads first.
    }
}

extern "C" void kernel_launch(void* const* d_in, const int* in_sizes, int n_in,
                              void* d_out, int out_size)
{
    const float* positions = (const float*)d_in[0];
    // d_in[1]: atomic_subsystem_indices (int32) — static layout, unused.
    float* out = (float*)d_out;

    pairlist_kernel<<<N_MOL, NTHREADS>>>(positions, out);
}

// round 4
// speedup vs baseline: 1.0936x; 1.0936x over previous
#include <cuda_runtime.h>
#include <cuda_bf16.h>

// Problem constants (static per reference)
#define N_MOL    2000
#define ASZ      64
#define PPM      (ASZ * (ASZ - 1))          // 4032 pairs per molecule
#define NPAIR    ((long long)N_MOL * PPM)   // 8,064,000
#define NTHREADS 252
#define NITER    4                          // 252 threads * 4 iters * 4 pairs = 4032

// Output layout (flattened tuple concat, fp32):
//   [0   ,  P) : i indices (as float)
//   [P   , 2P) : j indices (as float)
//   [2P  , 3P) : d_ij
//   [3P  , 6P) : r_ij row-major [P,3]

__global__ __launch_bounds__(NTHREADS)
void pairlist_kernel(const float* __restrict__ pos, float* __restrict__ out)
{
    __shared__ float s[ASZ * 3];   // xyz interleaved; LDS reads are near-broadcast

    const int m = blockIdx.x;
    const int t = threadIdx.x;

    // Stage this molecule's 64 positions (192 floats) into shared
    const float* pm = pos + (size_t)m * (ASZ * 3);
    if (t < ASZ * 3) s[t] = pm[t];
    __syncthreads();

    float* __restrict__ out_i = out;
    float* __restrict__ out_j = out + NPAIR;
    float* __restrict__ out_d = out + 2 * NPAIR;
    float* __restrict__ out_r = out + 3 * NPAIR;

    const size_t base  = (size_t)m * PPM;
    const int    ibase = m * ASZ;

    #pragma unroll
    for (int it = 0; it < NITER; it++) {
        const unsigned q0 = 4u * (unsigned)t + (unsigned)(4 * NTHREADS) * it;

        float fi[4], fj[4], fd[4], rr[12];

        #pragma unroll
        for (int u = 0; u < 4; u++) {
            const unsigned q     = q0 + u;
            const unsigned i_loc = q / 63u;              // magic-mul division
            const unsigned k     = q - 63u * i_loc;
            const unsigned j_loc = k + (k >= i_loc ? 1u : 0u);

            const float rx = s[3 * j_loc + 0] - s[3 * i_loc + 0];
            const float ry = s[3 * j_loc + 1] - s[3 * i_loc + 1];
            const float rz = s[3 * j_loc + 2] - s[3 * i_loc + 2];

            fi[u] = (float)(ibase + (int)i_loc);
            fj[u] = (float)(ibase + (int)j_loc);
            fd[u] = sqrtf(fmaf(rx, rx, fmaf(ry, ry, rz * rz)));
            rr[3 * u + 0] = rx;
            rr[3 * u + 1] = ry;
            rr[3 * u + 2] = rz;
        }

        const size_t p = base + q0;                      // multiple of 4 -> 16B aligned

        *(float4*)(out_i + p) = make_float4(fi[0], fi[1], fi[2], fi[3]);
        *(float4*)(out_j + p) = make_float4(fj[0], fj[1], fj[2], fj[3]);
        *(float4*)(out_d + p) = make_float4(fd[0], fd[1], fd[2], fd[3]);

        float4* rv = (float4*)(out_r + 3 * p);           // 12p bytes: 16B aligned
        rv[0] = make_float4(rr[0], rr[1], rr[2],  rr[3]);
        rv[1] = make_float4(rr[4], rr[5], rr[6],  rr[7]);
        rv[2] = make_float4(rr[8], rr[9], rr[10], rr[11]);
    }
}

extern "C" void kernel_launch(void* const* d_in, const int* in_sizes, int n_in,
                              void* d_out, int out_size)
{
    const float* positions = (const float*)d_in[0];
    // d_in[1]: atomic_subsystem_indices (int32) — static layout, unused.
    float* out = (float*)d_out;

    pairlist_kernel<<<N_MOL, NTHREADS>>>(positions, out);
}

// round 5
// speedup vs baseline: 1.0995x; 1.0054x over previous
#include <cuda_runtime.h>
#include <cuda_bf16.h>

// Problem constants (static per reference)
#define N_MOL    2000
#define ASZ      64
#define PPM      (ASZ * (ASZ - 1))          // 4032 pairs per molecule
#define NPAIR    ((long long)N_MOL * PPM)   // 8,064,000
#define NTHREADS 252
#define NITER    8                          // 252 threads * 8 iters * 2 pairs = 4032

// Output layout (flattened tuple concat, fp32):
//   [0   ,  P) : i indices (as float)
//   [P   , 2P) : j indices (as float)
//   [2P  , 3P) : d_ij
//   [3P  , 6P) : r_ij row-major [P,3]

__global__ __launch_bounds__(NTHREADS)
void pairlist_kernel(const float* __restrict__ pos, float* __restrict__ out)
{
    __shared__ float s[ASZ * 3];   // xyz interleaved; bank = (3a+c) mod 32

    const int m = blockIdx.x;
    const int t = threadIdx.x;

    // Stage this molecule's 64 positions (192 floats) into shared
    const float* pm = pos + (size_t)m * (ASZ * 3);
    if (t < ASZ * 3) s[t] = pm[t];
    __syncthreads();

    float* __restrict__ out_i = out;
    float* __restrict__ out_j = out + NPAIR;
    float* __restrict__ out_d = out + 2 * NPAIR;
    float* __restrict__ out_r = out + 3 * NPAIR;

    const size_t base  = (size_t)m * PPM;
    const int    ibase = m * ASZ;

    #pragma unroll 2
    for (int it = 0; it < NITER; it++) {
        // thread's 2 consecutive pairs; lanes within warp step by 2 pairs
        const unsigned q0 = 2u * ((unsigned)t + (unsigned)NTHREADS * it);

        float fi[2], fj[2], fd[2], rr[6];

        #pragma unroll
        for (int u = 0; u < 2; u++) {
            const unsigned q     = q0 + u;
            const unsigned i_loc = q / 63u;              // magic-mul division
            const unsigned k     = q - 63u * i_loc;
            const unsigned j_loc = k + (k >= i_loc ? 1u : 0u);

            // i-reads: near-broadcast; j-reads: lane addr step 6 -> 2-way max
            const float rx = s[3 * j_loc + 0] - s[3 * i_loc + 0];
            const float ry = s[3 * j_loc + 1] - s[3 * i_loc + 1];
            const float rz = s[3 * j_loc + 2] - s[3 * i_loc + 2];

            fi[u] = (float)(ibase + (int)i_loc);
            fj[u] = (float)(ibase + (int)j_loc);
            fd[u] = sqrtf(fmaf(rx, rx, fmaf(ry, ry, rz * rz)));
            rr[3 * u + 0] = rx;
            rr[3 * u + 1] = ry;
            rr[3 * u + 2] = rz;
        }

        const size_t p = base + q0;                      // even -> 8B aligned

        *(float2*)(out_i + p) = make_float2(fi[0], fi[1]);
        *(float2*)(out_j + p) = make_float2(fj[0], fj[1]);
        *(float2*)(out_d + p) = make_float2(fd[0], fd[1]);

        // r_ij: 24 contiguous bytes per thread, warp-dense -> 3 STG.64, 2 wf each
        float2* rv = (float2*)(out_r + 3 * p);           // byte 24t: 8B aligned
        rv[0] = make_float2(rr[0], rr[1]);
        rv[1] = make_float2(rr[2], rr[3]);
        rv[2] = make_float2(rr[4], rr[5]);
    }
}

extern "C" void kernel_launch(void* const* d_in, const int* in_sizes, int n_in,
                              void* d_out, int out_size)
{
    const float* positions = (const float*)d_in[0];
    // d_in[1]: atomic_subsystem_indices (int32) — static layout, unused.
    float* out = (float*)d_out;

    pairlist_kernel<<<N_MOL, NTHREADS>>>(positions, out);
}